// round 7
// baseline (speedup 1.0000x reference)
#include <cuda_runtime.h>

#define HID   51
#define GATES 204
#define ROWS  205           // + fused FC row
#define SEQ   999
#define BATCH 4096
#define BT    16            // batch per tile
#define TILES 2
#define BCTA  (BT * TILES)  // 32
#define NBLK  (BATCH / BCTA)// 128 CTAs, exact
#define NTHR  832           // 26 warps = 208 (row) x 4 (bq) slots
#define CHUNK 37            // 999 = 27*37
#define GP    20            // gates row stride (words): 16B-aligned float4 slots

// dynamic smem layout (floats)
#define H_OFF 0
#define H_SZ  (TILES * HID * BT)        // 1632
#define G_OFF (H_OFF + H_SZ)
#define G_SZ  (TILES * GATES * GP)      // 8160
#define X_OFF (G_OFF + G_SZ)
#define X_SZ  (TILES * BT * CHUNK)      // 1184
#define SMEM_FLOATS (X_OFF + X_SZ)      // 10976 -> 43904 bytes

typedef unsigned long long u64;

__device__ __forceinline__ u64 pack2(float a, float b) {
    u64 r; asm("mov.b64 %0,{%1,%2};" : "=l"(r) : "f"(a), "f"(b)); return r;
}
__device__ __forceinline__ void unpack2(float& a, float& b, u64 p) {
    asm("mov.b64 {%0,%1},%2;" : "=f"(a), "=f"(b) : "l"(p));
}
__device__ __forceinline__ u64 ffma2(u64 a, u64 b, u64 c) {
    u64 d; asm("fma.rn.f32x2 %0,%1,%2,%3;" : "=l"(d) : "l"(a), "l"(b), "l"(c)); return d;
}

__device__ __forceinline__ float sigf(float x) {
    return __fdividef(1.0f, 1.0f + __expf(-x));        // saturation-safe
}
__device__ __forceinline__ float tanh_(float x) {
    return __fdividef(2.0f, 1.0f + __expf(-2.0f * x)) - 1.0f;
}

__global__ __launch_bounds__(NTHR, 1)
void lstm_persistent(const float* __restrict__ input,
                     const float* __restrict__ W_ih,
                     const float* __restrict__ W_hh,
                     const float* __restrict__ b_ih,
                     const float* __restrict__ b_hh,
                     const float* __restrict__ W_fc,
                     const float* __restrict__ b_fc,
                     float* __restrict__ out)
{
    extern __shared__ float sm[];
    const int tid   = threadIdx.x;
    const int rowid = tid >> 2;          // 0..207 (205..207 idle in GEMM)
    const int bq    = tid & 3;           // batch quad within tile
    const int b0    = blockIdx.x * BCTA;

    // ---- row weights in registers (duplicated across the 4 bq threads) ----
    float whh[HID];
    float bias = 0.0f, wih = 0.0f;
    if (rowid < GATES) {
        bias = b_ih[rowid] + b_hh[rowid];
        wih  = W_ih[rowid];                          // INPUT == 1
        #pragma unroll
        for (int j = 0; j < HID; j++) whh[j] = W_hh[rowid * HID + j];
    } else if (rowid == GATES) {                     // fused FC row
        bias = b_fc[0];
        #pragma unroll
        for (int j = 0; j < HID; j++) whh[j] = W_fc[j];
    } else {
        #pragma unroll
        for (int j = 0; j < HID; j++) whh[j] = 0.0f;
    }

    for (int e = tid; e < H_SZ; e += NTHR) sm[H_OFF + e] = 0.0f;

    // elementwise mapping (tid < 816): k = tid>>4, b = tid&15, per tile
    const int ewk = tid >> 4, ewb = tid & 15;
    float creg[TILES] = {0.0f, 0.0f};

    const bool is_gate = (rowid < GATES);
    const bool is_fc   = (rowid == GATES);

    for (int t = 0; t <= SEQ; ++t) {
        if (t < SEQ && (t % CHUNK) == 0) {           // stage input chunk, both tiles
            for (int e = tid; e < X_SZ; e += NTHR) {
                int tile = e / (BT * CHUNK);
                int rem  = e - tile * (BT * CHUNK);
                int b = rem / CHUNK, tc = rem - b * CHUNK;
                sm[X_OFF + e] = input[(size_t)(b0 + tile * BT + b) * SEQ + (t + tc)];
            }
        }
        __syncthreads();   // A: h(t-1), x ready

        // ---- GEMM: rows 0..203 -> gates_t ; row 204 -> y_{t-1} ----
        const bool act = is_gate ? (t < SEQ) : (is_fc && t > 0);
        if (act) {
            const int tc = t % CHUNK;
            #pragma unroll 1                          // keep tiles sharing code: no wp hoisting
            for (int tile = 0; tile < TILES; tile++) {
                const float* xb = sm + X_OFF + tile * (BT * CHUNK) + (bq * 4) * CHUNK + tc;
                u64 a0 = pack2(fmaf(wih, xb[0],         bias),
                               fmaf(wih, xb[CHUNK],     bias));
                u64 a1 = pack2(fmaf(wih, xb[2 * CHUNK], bias),
                               fmaf(wih, xb[3 * CHUNK], bias));
                const float* hb = sm + H_OFF + tile * (HID * BT) + bq * 4;
                #pragma unroll
                for (int k = 0; k < HID; k++) {
                    u64 wp = pack2(whh[k], whh[k]);
                    ulonglong2 hp = *reinterpret_cast<const ulonglong2*>(hb + k * BT);
                    a0 = ffma2(hp.x, wp, a0);         // 1 wavefront LDS feeds 4 FMAs...
                    a1 = ffma2(hp.y, wp, a1);         // ...x8-row broadcast across warp
                }
                float o0, o1, o2, o3;
                unpack2(o0, o1, a0); unpack2(o2, o3, a1);
                if (is_gate) {
                    *reinterpret_cast<float4*>(
                        sm + G_OFF + tile * (GATES * GP) + rowid * GP + bq * 4)
                        = make_float4(o0, o1, o2, o3);
                } else {                               // FC: y_{t-1} for 4 batch cols
                    size_t ob = (size_t)(b0 + tile * BT + bq * 4) * SEQ + (t - 1);
                    out[ob]           = o0;
                    out[ob + SEQ]     = o1;
                    out[ob + 2 * SEQ] = o2;
                    out[ob + 3 * SEQ] = o3;
                }
            }
        }
        __syncthreads();   // B: gates ready; GEMM done reading h(t-1)

        // ---- elementwise cell update -> h(t), both tiles ----
        if (t < SEQ && tid < HID * BT) {
            #pragma unroll
            for (int tile = 0; tile < TILES; tile++) {
                const float* gb = sm + G_OFF + tile * (GATES * GP);
                float gi = gb[(ewk          ) * GP + ewb];
                float gf = gb[(ewk +     HID) * GP + ewb];
                float gg = gb[(ewk + 2 * HID) * GP + ewb];
                float go = gb[(ewk + 3 * HID) * GP + ewb];
                float c  = sigf(gf) * creg[tile] + sigf(gi) * tanh_(gg);
                creg[tile] = c;
                sm[H_OFF + tile * (HID * BT) + ewk * BT + ewb] = sigf(go) * tanh_(c);
            }
        }
    }
}

extern "C" void kernel_launch(void* const* d_in, const int* in_sizes, int n_in,
                              void* d_out, int out_size) {
    const float* input = (const float*)d_in[0];
    const float* W_ih  = (const float*)d_in[1];
    const float* W_hh  = (const float*)d_in[2];
    const float* b_ih  = (const float*)d_in[3];
    const float* b_hh  = (const float*)d_in[4];
    const float* W_fc  = (const float*)d_in[5];
    const float* b_fc  = (const float*)d_in[6];

    cudaFuncSetAttribute(lstm_persistent,
                         cudaFuncAttributeMaxDynamicSharedMemorySize,
                         SMEM_FLOATS * (int)sizeof(float));
    lstm_persistent<<<NBLK, NTHR, SMEM_FLOATS * sizeof(float)>>>(
        input, W_ih, W_hh, b_ih, b_hh, W_fc, b_fc, (float*)d_out);
}

// round 8
// speedup vs baseline: 1.3831x; 1.3831x over previous
#include <cuda_runtime.h>

#define HID   51
#define GATES 204
#define SEQ   999
#define BATCH 4096
#define BT    14           // batch rows per block
#define NBLK  ((BATCH + BT - 1) / BT)   // 293
#define CHUNK 111          // 999 = 9*111
#define HPAD  52           // h row stride (13 float4)
#define GPAD  15           // gates row stride (R1-proven conflict-free)
#define KSPL  28           // k-split point (s=0: 7 quads, s=1: 6 quads)

__device__ __forceinline__ float sigf(float x) {
    return __fdividef(1.0f, 1.0f + __expf(-x));        // saturation-safe
}
__device__ __forceinline__ float tanh_(float x) {
    return __fdividef(2.0f, 1.0f + __expf(-2.0f * x)) - 1.0f;
}

__global__ __launch_bounds__(512, 2)
void lstm_persistent(const float* __restrict__ input,
                     const float* __restrict__ W_ih,
                     const float* __restrict__ W_hh,
                     const float* __restrict__ b_ih,
                     const float* __restrict__ b_hh,
                     const float* __restrict__ W_fc,
                     const float* __restrict__ b_fc,
                     float* __restrict__ out)
{
    __shared__ float h_sh[BT * HPAD];            // h_{t-1}, pad cols stay 0
    __shared__ float gates_sh[GATES * GPAD];     // [gate_row][b]
    __shared__ float x_sh[BT * CHUNK];           // input chunk

    const int tid   = threadIdx.x;
    const int rowid = tid >> 1;                  // 0..255 (208..255 never in GEMM warps)
    const int s     = tid & 1;                   // k-split half
    const int b0    = blockIdx.x * BT;
    const int B_local = min(BT, BATCH - b0);     // 14, or 8 on last block

    // ---- half-row weights in registers ----
    // s=0: k in [0,28), 7 quads ; s=1: k in [28,52), 6 quads (k=51 pad -> 0)
    float whh[KSPL];
    float bias = 0.0f, wih = 0.0f;
    {
        const int kbase = s * KSPL;
        #pragma unroll
        for (int j = 0; j < KSPL; j++) whh[j] = 0.0f;
        if (rowid < GATES) {
            if (s == 0) { bias = b_ih[rowid] + b_hh[rowid]; wih = W_ih[rowid]; }
            #pragma unroll
            for (int j = 0; j < KSPL; j++) {
                int k = kbase + j;
                if (k < HID) whh[j] = W_hh[rowid * HID + k];
            }
        } else if (rowid == GATES) {             // fused FC row
            if (s == 0) bias = b_fc[0];
            #pragma unroll
            for (int j = 0; j < KSPL; j++) {
                int k = kbase + j;
                if (k < HID) whh[j] = W_fc[k];
            }
        }
    }
    const int nq = 7 - s;                        // quads this half owns

    for (int e = tid; e < BT * HPAD; e += 512) h_sh[e] = 0.0f;

    // elementwise mapping: e = tid, tid+512 ; b = e/HID, k = e%HID
    int eb[2], ek[2];
    float creg[2] = {0.0f, 0.0f};
    #pragma unroll
    for (int r = 0; r < 2; r++) {
        int e = tid + 512 * r;
        eb[r] = e / HID;
        ek[r] = e - eb[r] * HID;
    }

    const bool in_gemm  = (tid < 416);           // warps 0..12 (rows 0..207)
    const bool is_gate  = (rowid < GATES);
    const bool is_fc    = (rowid == GATES);

    for (int t = 0; t <= SEQ; ++t) {
        if (t < SEQ && (t % CHUNK) == 0) {       // stage input chunk
            int n = B_local * CHUNK;
            for (int e = tid; e < n; e += 512) {
                int b  = e / CHUNK;
                int tc = e - b * CHUNK;
                x_sh[e] = input[(size_t)(b0 + b) * SEQ + (t + tc)];
            }
        }
        __syncthreads();   // A: h(t-1), x ready

        // ---- GEMM: all 13 warps run every step (whfl-safe, zero-weight dummies) ----
        if (in_gemm) {
            const int tc = t % CHUNK;
            const bool g_store  = is_gate && (s == 0) && (t < SEQ);
            const bool fc_store = is_fc   && (s == 0) && (t > 0);
            for (int b = 0; b < B_local; b += 2) {
                float a0, a1;
                if (s == 0) {
                    a0 = fmaf(wih, x_sh[b * CHUNK + tc], bias);
                    a1 = fmaf(wih, x_sh[(b + 1) * CHUNK + tc], bias);
                } else {
                    a0 = 0.0f; a1 = 0.0f;
                }
                const float4* h40 =
                    reinterpret_cast<const float4*>(h_sh + b * HPAD + s * KSPL);
                const float4* h41 =
                    reinterpret_cast<const float4*>(h_sh + (b + 1) * HPAD + s * KSPL);
                #pragma unroll
                for (int q = 0; q < 7; q++) {
                    if (q < nq) {
                        float4 u = h40[q];
                        float4 v = h41[q];
                        a0 = fmaf(u.x, whh[4 * q + 0], a0);
                        a1 = fmaf(v.x, whh[4 * q + 0], a1);
                        a0 = fmaf(u.y, whh[4 * q + 1], a0);
                        a1 = fmaf(v.y, whh[4 * q + 1], a1);
                        a0 = fmaf(u.z, whh[4 * q + 2], a0);
                        a1 = fmaf(v.z, whh[4 * q + 2], a1);
                        a0 = fmaf(u.w, whh[4 * q + 3], a0);
                        a1 = fmaf(v.w, whh[4 * q + 3], a1);
                    }
                }
                // combine the two k-halves (partner lane = tid^1)
                a0 += __shfl_xor_sync(0xFFFFFFFFu, a0, 1);
                a1 += __shfl_xor_sync(0xFFFFFFFFu, a1, 1);
                if (g_store) {
                    gates_sh[rowid * GPAD + b]     = a0;
                    gates_sh[rowid * GPAD + b + 1] = a1;
                } else if (fc_store) {
                    out[(size_t)(b0 + b)     * SEQ + (t - 1)] = a0;
                    out[(size_t)(b0 + b + 1) * SEQ + (t - 1)] = a1;
                }
            }
        }
        __syncthreads();   // B: gates ready; GEMM done reading h(t-1)

        // ---- elementwise cell update -> h(t) ----
        if (t < SEQ) {
            #pragma unroll
            for (int r = 0; r < 2; r++) {
                int e = tid + 512 * r;
                if (e < B_local * HID) {
                    int b = eb[r], k = ek[r];
                    float gi = gates_sh[(k          ) * GPAD + b];
                    float gf = gates_sh[(k +     HID) * GPAD + b];
                    float gg = gates_sh[(k + 2 * HID) * GPAD + b];
                    float go = gates_sh[(k + 3 * HID) * GPAD + b];
                    float c  = sigf(gf) * creg[r] + sigf(gi) * tanh_(gg);
                    creg[r]  = c;
                    h_sh[b * HPAD + k] = sigf(go) * tanh_(c);
                }
            }
        }
    }
}

extern "C" void kernel_launch(void* const* d_in, const int* in_sizes, int n_in,
                              void* d_out, int out_size) {
    const float* input = (const float*)d_in[0];
    const float* W_ih  = (const float*)d_in[1];
    const float* W_hh  = (const float*)d_in[2];
    const float* b_ih  = (const float*)d_in[3];
    const float* b_hh  = (const float*)d_in[4];
    const float* W_fc  = (const float*)d_in[5];
    const float* b_fc  = (const float*)d_in[6];
    lstm_persistent<<<NBLK, 512>>>(input, W_ih, W_hh, b_ih, b_hh, W_fc, b_fc,
                                   (float*)d_out);
}

// round 10
// speedup vs baseline: 1.3878x; 1.0034x over previous
#include <cuda_runtime.h>

#define HID   51
#define GATES 204
#define SEQ   999
#define BATCH 4096
#define BT    14
#define CHUNK 111          // 999 = 9*111
#define HPAD  56           // h row stride; k pads 51..55 = 0
#define KH    28           // k-half (7 float4 quads)
#define PPAD  104          // p-dim stride of partial arrays (p in 0..103)

__device__ __forceinline__ float sigf(float x) {
    return __fdividef(1.0f, 1.0f + __expf(-x));        // saturation-safe
}
__device__ __forceinline__ float tanh_(float x) {
    return __fdividef(2.0f, 1.0f + __expf(-2.0f * x)) - 1.0f;
}

// thread (p, s): owns gate rows (2p, 2p+1), k in [28s, 28s+28)
// warps 0..3: s=0, warps 4..7: s=1  -> s warp-uniform, addresses broadcast
template<int BL>
__global__ __launch_bounds__(256, 2)
void lstm_kernel(const float* __restrict__ input,
                 const float* __restrict__ W_ih,
                 const float* __restrict__ W_hh,
                 const float* __restrict__ b_ih,
                 const float* __restrict__ b_hh,
                 const float* __restrict__ W_fc,
                 const float* __restrict__ b_fc,
                 float* __restrict__ out,
                 int b0_base)
{
    __shared__ float h_sh[BL * HPAD];          // h(t-1); k-pad cols stay 0
    __shared__ float gA[2 * BL * PPAD];        // partial of even row 2p   [s][b][p]
    __shared__ float gB[2 * BL * PPAD];        // partial of odd  row 2p+1
    __shared__ float x_sh[BL * CHUNK];

    const int tid = threadIdx.x;
    const int p   = tid & 127;                 // 0..127 (104..127 dummy)
    const int s   = tid >> 7;                  // k-half, warp-uniform
    const int b0  = b0_base + blockIdx.x * BL;

    // ---- per-thread half-row weights for rows r0=2p, r1=2p+1 ----
    float w0[KH], w1[KH];
    float bias0 = 0.f, bias1 = 0.f, wih0 = 0.f, wih1 = 0.f;
    {
        const int r0 = 2 * p, r1 = 2 * p + 1;
        #pragma unroll
        for (int j = 0; j < KH; j++) { w0[j] = 0.f; w1[j] = 0.f; }
        if (r0 < GATES) {
            if (s == 0) { bias0 = b_ih[r0] + b_hh[r0]; wih0 = W_ih[r0]; }
            #pragma unroll
            for (int j = 0; j < KH; j++) {
                int k = s * KH + j;
                if (k < HID) w0[j] = W_hh[r0 * HID + k];
            }
        } else if (r0 == GATES) {              // fused FC row
            if (s == 0) bias0 = b_fc[0];
            #pragma unroll
            for (int j = 0; j < KH; j++) {
                int k = s * KH + j;
                if (k < HID) w0[j] = W_fc[k];
            }
        }
        if (r1 < GATES) {
            if (s == 0) { bias1 = b_ih[r1] + b_hh[r1]; wih1 = W_ih[r1]; }
            #pragma unroll
            for (int j = 0; j < KH; j++) {
                int k = s * KH + j;
                if (k < HID) w1[j] = W_hh[r1 * HID + k];
            }
        }
    }

    for (int e = tid; e < BL * HPAD; e += 256) h_sh[e] = 0.0f;

    // elementwise mapping: e = tid + 256*r ; b = e/51, k = e%51
    float creg[3] = {0.f, 0.f, 0.f};

    const bool pa = (p < PPAD);                // store guard for dummies

    for (int t = 0; t <= SEQ; ++t) {
        if (t < SEQ && (t % CHUNK) == 0) {
            #pragma unroll 1
            for (int e = tid; e < BL * CHUNK; e += 256) {
                int b = e / CHUNK, tc = e - b * CHUNK;
                x_sh[e] = input[(size_t)(b0 + b) * SEQ + (t + tc)];
            }
        }
        __syncthreads();   // A: h(t-1), x ready

        // ---- GEMM: partial dot over this thread's k-half, rows 2p & 2p+1 ----
        {
            const int tc = t % CHUNK;
            #pragma unroll
            for (int bb = 0; bb < BL / 2; bb++) {
                const int b = 2 * bb;
                float a00, a01, a10, a11;      // a[row][batch]
                if (s == 0) {
                    float xb0 = x_sh[b * CHUNK + tc];
                    float xb1 = x_sh[(b + 1) * CHUNK + tc];
                    a00 = fmaf(wih0, xb0, bias0);
                    a01 = fmaf(wih0, xb1, bias0);
                    a10 = fmaf(wih1, xb0, bias1);
                    a11 = fmaf(wih1, xb1, bias1);
                } else {
                    a00 = a01 = a10 = a11 = 0.f;
                }
                const float4* h0 =
                    reinterpret_cast<const float4*>(h_sh + b * HPAD + s * KH);
                const float4* h1 =
                    reinterpret_cast<const float4*>(h_sh + (b + 1) * HPAD + s * KH);
                #pragma unroll
                for (int q = 0; q < 7; q++) {
                    float4 u = h0[q];          // 1 LDS.128 feeds 8 FMAs
                    float4 v = h1[q];
                    a00 = fmaf(u.x, w0[4*q+0], a00); a10 = fmaf(u.x, w1[4*q+0], a10);
                    a01 = fmaf(v.x, w0[4*q+0], a01); a11 = fmaf(v.x, w1[4*q+0], a11);
                    a00 = fmaf(u.y, w0[4*q+1], a00); a10 = fmaf(u.y, w1[4*q+1], a10);
                    a01 = fmaf(v.y, w0[4*q+1], a01); a11 = fmaf(v.y, w1[4*q+1], a11);
                    a00 = fmaf(u.z, w0[4*q+2], a00); a10 = fmaf(u.z, w1[4*q+2], a10);
                    a01 = fmaf(v.z, w0[4*q+2], a01); a11 = fmaf(v.z, w1[4*q+2], a11);
                    a00 = fmaf(u.w, w0[4*q+3], a00); a10 = fmaf(u.w, w1[4*q+3], a10);
                    a01 = fmaf(v.w, w0[4*q+3], a01); a11 = fmaf(v.w, w1[4*q+3], a11);
                }
                if (pa) {                      // lane-consecutive p: conflict-free
                    gA[(s * BL + b)     * PPAD + p] = a00;
                    gB[(s * BL + b)     * PPAD + p] = a10;
                    gA[(s * BL + b + 1) * PPAD + p] = a01;
                    gB[(s * BL + b + 1) * PPAD + p] = a11;
                }
            }
        }
        __syncthreads();   // B: partials ready; GEMM done reading h(t-1)

        // ---- fused FC output: row 204 lives at gA[.][b][102] ----
        if (t > 0 && tid < BL) {
            float y = gA[(0 * BL + tid) * PPAD + 102]
                    + gA[(1 * BL + tid) * PPAD + 102];
            out[(size_t)(b0 + tid) * SEQ + (t - 1)] = y;
        }

        // ---- elementwise cell update -> h(t) ----
        if (t < SEQ) {
            #pragma unroll
            for (int r = 0; r < 3; r++) {
                int e = tid + 256 * r;
                if (e < BL * HID) {
                    int b = e / HID, k = e - b * HID;
                    int ri = k,            pi = ri >> 1;
                    int rf = k +     HID,  pf = rf >> 1;
                    int rg = k + 2 * HID,  pg = rg >> 1;
                    int ro = k + 3 * HID,  po = ro >> 1;
                    const float* Ai = (ri & 1) ? gB : gA;
                    const float* Af = (rf & 1) ? gB : gA;
                    const float* Ag = (rg & 1) ? gB : gA;
                    const float* Ao = (ro & 1) ? gB : gA;
                    float gi = Ai[b * PPAD + pi] + Ai[(BL + b) * PPAD + pi];
                    float gf = Af[b * PPAD + pf] + Af[(BL + b) * PPAD + pf];
                    float gg = Ag[b * PPAD + pg] + Ag[(BL + b) * PPAD + pg];
                    float go = Ao[b * PPAD + po] + Ao[(BL + b) * PPAD + po];
                    float c  = sigf(gf) * creg[r] + sigf(gi) * tanh_(gg);
                    creg[r]  = c;
                    h_sh[b * HPAD + k] = sigf(go) * tanh_(c);
                }
            }
        }
    }
}

extern "C" void kernel_launch(void* const* d_in, const int* in_sizes, int n_in,
                              void* d_out, int out_size) {
    const float* input = (const float*)d_in[0];
    const float* W_ih  = (const float*)d_in[1];
    const float* W_hh  = (const float*)d_in[2];
    const float* b_ih  = (const float*)d_in[3];
    const float* b_hh  = (const float*)d_in[4];
    const float* W_fc  = (const float*)d_in[5];
    const float* b_fc  = (const float*)d_in[6];
    float* out = (float*)d_out;

    // 4096 = 292*14 + 8 : main grid fully unrolled at BL=14, tail block BL=8
    lstm_kernel<14><<<292, 256>>>(input, W_ih, W_hh, b_ih, b_hh, W_fc, b_fc, out, 0);
    lstm_kernel<8><<<1, 256>>>(input, W_ih, W_hh, b_ih, b_hh, W_fc, b_fc, out, 292 * BT);
}

// round 15
// speedup vs baseline: 1.6199x; 1.1673x over previous
#include <cuda_runtime.h>

#define HID   51
#define GATES 204
#define SEQ   999
#define BATCH 4096
#define BT    16           // 4096/16 = 256 CTAs, NO tail
#define NBLK  (BATCH / BT)
#define CHUNK 111          // 999 = 9*111
#define HPAD  52           // h row stride: 208 B, 16B-aligned rows; col 51 = 0 pad
#define GPAD  17           // gates row stride, coprime with 32 -> conflict-free

typedef unsigned long long u64;

__device__ __forceinline__ u64 pack2(float a, float b) {
    u64 r; asm("mov.b64 %0,{%1,%2};" : "=l"(r) : "f"(a), "f"(b)); return r;
}
__device__ __forceinline__ void unpack2(float& a, float& b, u64 p) {
    asm("mov.b64 {%0,%1},%2;" : "=f"(a), "=f"(b) : "l"(p));
}
__device__ __forceinline__ u64 ffma2(u64 a, u64 b, u64 c) {
    u64 d; asm("fma.rn.f32x2 %0,%1,%2,%3;" : "=l"(d) : "l"(a), "l"(b), "l"(c)); return d;
}

__device__ __forceinline__ float sigf(float x) {
    return __fdividef(1.0f, 1.0f + __expf(-x));        // saturation-safe
}
__device__ __forceinline__ float tanh_(float x) {
    return __fdividef(2.0f, 1.0f + __expf(-2.0f * x)) - 1.0f;
}

__global__ __launch_bounds__(256, 2)
void lstm_persistent(const float* __restrict__ input,
                     const float* __restrict__ W_ih,
                     const float* __restrict__ W_hh,
                     const float* __restrict__ b_ih,
                     const float* __restrict__ b_hh,
                     const float* __restrict__ W_fc,
                     const float* __restrict__ b_fc,
                     float* __restrict__ out)
{
    __shared__ __align__(16) float h_sh[BT * HPAD];   // h(t-1); k=51 col stays 0
    __shared__ float gates_sh[GATES * GPAD];          // [gate_row][b]
    __shared__ float x_sh[BT * CHUNK];                // input chunk

    const int tid = threadIdx.x;                      // thread == gate row
    const int b0  = blockIdx.x * BT;

    // ---- per-row weights, PRE-PACKED even/odd pairs (k=2j, 2j+1), once ----
    u64 wp[26];
    float bias = 0.0f, wih = 0.0f;
    if (tid < GATES) {
        bias = b_ih[tid] + b_hh[tid];
        wih  = W_ih[tid];                             // INPUT == 1
        const float* wr = W_hh + tid * HID;
        #pragma unroll
        for (int j = 0; j < 25; j++) wp[j] = pack2(wr[2 * j], wr[2 * j + 1]);
        wp[25] = pack2(wr[50], 0.0f);                 // pairs with h[51]=0 pad
    } else if (tid == GATES) {                        // fused FC row
        bias = b_fc[0];
        #pragma unroll
        for (int j = 0; j < 25; j++) wp[j] = pack2(W_fc[2 * j], W_fc[2 * j + 1]);
        wp[25] = pack2(W_fc[50], 0.0f);
    } else {
        #pragma unroll
        for (int j = 0; j < 26; j++) wp[j] = 0ull;
    }

    for (int e = tid; e < BT * HPAD; e += 256) h_sh[e] = 0.0f;

    // elementwise mapping: e = tid + 256*r ; b = e/51, k = e%51 ; 816 elems
    int eb[4], ek[4];
    float creg[4] = {0.f, 0.f, 0.f, 0.f};
    #pragma unroll
    for (int r = 0; r < 4; r++) {
        int e = tid + 256 * r;
        eb[r] = e / HID;
        ek[r] = e - eb[r] * HID;
    }

    const bool is_gate = (tid < GATES);
    const bool is_fc   = (tid == GATES);

    for (int t = 0; t <= SEQ; ++t) {
        if (t < SEQ && (t % CHUNK) == 0) {            // stage input chunk
            #pragma unroll 1
            for (int e = tid; e < BT * CHUNK; e += 256) {
                int b = e / CHUNK, tc = e - b * CHUNK;
                x_sh[e] = input[(size_t)(b0 + b) * SEQ + (t + tc)];
            }
        }
        __syncthreads();   // A: h(t-1), x ready

        // ---- GEMM: row dot h for 16 batch cols, f32x2 even/odd split ----
        const bool act = is_gate ? (t < SEQ) : (is_fc && (t > 0));
        if (act) {
            const int tc = t % CHUNK;
            #pragma unroll
            for (int bb = 0; bb < BT / 2; bb++) {
                const int b = 2 * bb;
                u64 accB = pack2(fmaf(wih, x_sh[b * CHUNK + tc], bias), 0.0f);
                u64 accC = pack2(fmaf(wih, x_sh[(b + 1) * CHUNK + tc], bias), 0.0f);
                const ulonglong2* hB =
                    reinterpret_cast<const ulonglong2*>(h_sh + b * HPAD);
                const ulonglong2* hC =
                    reinterpret_cast<const ulonglong2*>(h_sh + (b + 1) * HPAD);
                #pragma unroll
                for (int q = 0; q < 13; q++) {
                    ulonglong2 u = hB[q];             // (h[4q],h[4q+1]),(h[4q+2],h[4q+3])
                    ulonglong2 v = hC[q];
                    accB = ffma2(u.x, wp[2 * q],     accB);
                    accB = ffma2(u.y, wp[2 * q + 1], accB);
                    accC = ffma2(v.x, wp[2 * q],     accC);
                    accC = ffma2(v.y, wp[2 * q + 1], accC);
                }
                float blo, bhi, clo, chi;
                unpack2(blo, bhi, accB);
                unpack2(clo, chi, accC);
                const float gB = blo + bhi;           // horizontal combine
                const float gC = clo + chi;
                if (is_gate) {
                    gates_sh[tid * GPAD + b]     = gB;
                    gates_sh[tid * GPAD + b + 1] = gC;
                } else {                              // FC row -> y_{t-1}
                    out[(size_t)(b0 + b)     * SEQ + (t - 1)] = gB;
                    out[(size_t)(b0 + b + 1) * SEQ + (t - 1)] = gC;
                }
            }
        }
        __syncthreads();   // B: gates ready; GEMM done reading h(t-1)

        // ---- elementwise cell update -> h(t) ----
        if (t < SEQ) {
            #pragma unroll
            for (int r = 0; r < 4; r++) {
                int e = tid + 256 * r;
                if (e < BT * HID) {
                    int b = eb[r], k = ek[r];
                    float gi = gates_sh[(k          ) * GPAD + b];
                    float gf = gates_sh[(k +     HID) * GPAD + b];
                    float gg = gates_sh[(k + 2 * HID) * GPAD + b];
                    float go = gates_sh[(k + 3 * HID) * GPAD + b];
                    float c  = sigf(gf) * creg[r] + sigf(gi) * tanh_(gg);
                    creg[r]  = c;
                    h_sh[b * HPAD + k] = sigf(go) * tanh_(c);
                }
            }
        }
    }
}

extern "C" void kernel_launch(void* const* d_in, const int* in_sizes, int n_in,
                              void* d_out, int out_size) {
    const float* input = (const float*)d_in[0];
    const float* W_ih  = (const float*)d_in[1];
    const float* W_hh  = (const float*)d_in[2];
    const float* b_ih  = (const float*)d_in[3];
    const float* b_hh  = (const float*)d_in[4];
    const float* W_fc  = (const float*)d_in[5];
    const float* b_fc  = (const float*)d_in[6];
    lstm_persistent<<<NBLK, 256>>>(input, W_ih, W_hh, b_ih, b_hh, W_fc, b_fc,
                                   (float*)d_out);
}

// round 17
// speedup vs baseline: 2.0122x; 1.2422x over previous
#include <cuda_runtime.h>

#define HID   51
#define GATES 204
#define SEQ   999
#define BATCH 4096
#define BL    14
#define NBLK  293          // 292 full + 1 overlapping (b0 clamped)
#define CHUNK 111          // 999 = 9*111
#define HPAD  56           // h row stride; k pads 51..55 = 0
#define KH    28           // k-half (7 float4 quads)
#define PPAD  104          // p-dim stride of partial arrays (p in 0..103)

__device__ __forceinline__ float tanhg(float x) {
    float y; asm("tanh.approx.f32 %0,%1;" : "=f"(y) : "f"(x)); return y;
}
__device__ __forceinline__ float sigf(float x) {
    return fmaf(tanhg(0.5f * x), 0.5f, 0.5f);          // sig(x)=0.5*tanh(x/2)+0.5
}

// thread (p, s): owns gate rows (2p, 2p+1), k in [28s, 28s+28)
// warps 0..3: s=0, warps 4..7: s=1  -> s warp-uniform, h addresses broadcast
__global__ __launch_bounds__(256, 2)
void lstm_kernel(const float* __restrict__ input,
                 const float* __restrict__ W_ih,
                 const float* __restrict__ W_hh,
                 const float* __restrict__ b_ih,
                 const float* __restrict__ b_hh,
                 const float* __restrict__ W_fc,
                 const float* __restrict__ b_fc,
                 float* __restrict__ out)
{
    __shared__ __align__(16) float h_sh[BL * HPAD];   // h(t-1); k-pad cols stay 0
    __shared__ float gA[2 * BL * PPAD];               // partial, even row 2p   [s][b][p]
    __shared__ float gB[2 * BL * PPAD];               // partial, odd  row 2p+1
    __shared__ float x_sh[BL * CHUNK];

    const int tid = threadIdx.x;
    const int p   = tid & 127;                        // 0..127 (103..127 partly dummy)
    const int s   = tid >> 7;                         // k-half, warp-uniform
    const int b0  = min((int)blockIdx.x * BL, BATCH - BL);  // last block overlaps: benign dup

    // ---- per-thread half-row weights for rows r0=2p, r1=2p+1 ----
    float w0[KH], w1[KH];
    float bias0 = 0.f, bias1 = 0.f, wih0 = 0.f, wih1 = 0.f;
    {
        const int r0 = 2 * p, r1 = 2 * p + 1;
        #pragma unroll
        for (int j = 0; j < KH; j++) { w0[j] = 0.f; w1[j] = 0.f; }
        if (r0 < GATES) {
            if (s == 0) { bias0 = b_ih[r0] + b_hh[r0]; wih0 = W_ih[r0]; }
            #pragma unroll
            for (int j = 0; j < KH; j++) {
                int k = s * KH + j;
                if (k < HID) w0[j] = W_hh[r0 * HID + k];
            }
        } else if (r0 == GATES) {                     // fused FC row (p=102, r0=204)
            if (s == 0) bias0 = b_fc[0];
            #pragma unroll
            for (int j = 0; j < KH; j++) {
                int k = s * KH + j;
                if (k < HID) w0[j] = W_fc[k];
            }
        }
        if (r1 < GATES) {
            if (s == 0) { bias1 = b_ih[r1] + b_hh[r1]; wih1 = W_ih[r1]; }
            #pragma unroll
            for (int j = 0; j < KH; j++) {
                int k = s * KH + j;
                if (k < HID) w1[j] = W_hh[r1 * HID + k];
            }
        }
    }

    for (int e = tid; e < BL * HPAD; e += 256) h_sh[e] = 0.0f;

    float creg[3] = {0.f, 0.f, 0.f};                  // c-state, e = tid + 256*r
    const bool pa = (p < PPAD);                       // store guard for dummy lanes

    for (int t = 0; t <= SEQ; ++t) {
        if (t < SEQ && (t % CHUNK) == 0) {
            #pragma unroll 1
            for (int e = tid; e < BL * CHUNK; e += 256) {
                int b = e / CHUNK, tc = e - b * CHUNK;
                x_sh[e] = input[(size_t)(b0 + b) * SEQ + (t + tc)];
            }
        }
        __syncthreads();   // A: h(t-1), x ready

        // ---- GEMM: partial dot over this thread's k-half, rows 2p & 2p+1 ----
        {
            const int tc = t % CHUNK;
            #pragma unroll
            for (int bb = 0; bb < BL / 2; bb++) {
                const int b = 2 * bb;
                float a00, a01, a10, a11;             // a[row][batch]
                if (s == 0) {
                    float xb0 = x_sh[b * CHUNK + tc];
                    float xb1 = x_sh[(b + 1) * CHUNK + tc];
                    a00 = fmaf(wih0, xb0, bias0);
                    a01 = fmaf(wih0, xb1, bias0);
                    a10 = fmaf(wih1, xb0, bias1);
                    a11 = fmaf(wih1, xb1, bias1);
                } else {
                    a00 = a01 = a10 = a11 = 0.f;
                }
                const float4* h0 =
                    reinterpret_cast<const float4*>(h_sh + b * HPAD + s * KH);
                const float4* h1 =
                    reinterpret_cast<const float4*>(h_sh + (b + 1) * HPAD + s * KH);
                #pragma unroll
                for (int q = 0; q < 7; q++) {
                    float4 u = h0[q];                 // 1 broadcast LDS.128 -> 8 FMAs
                    float4 v = h1[q];
                    a00 = fmaf(u.x, w0[4*q+0], a00); a10 = fmaf(u.x, w1[4*q+0], a10);
                    a01 = fmaf(v.x, w0[4*q+0], a01); a11 = fmaf(v.x, w1[4*q+0], a11);
                    a00 = fmaf(u.y, w0[4*q+1], a00); a10 = fmaf(u.y, w1[4*q+1], a10);
                    a01 = fmaf(v.y, w0[4*q+1], a01); a11 = fmaf(v.y, w1[4*q+1], a11);
                    a00 = fmaf(u.z, w0[4*q+2], a00); a10 = fmaf(u.z, w1[4*q+2], a10);
                    a01 = fmaf(v.z, w0[4*q+2], a01); a11 = fmaf(v.z, w1[4*q+2], a11);
                    a00 = fmaf(u.w, w0[4*q+3], a00); a10 = fmaf(u.w, w1[4*q+3], a10);
                    a01 = fmaf(v.w, w0[4*q+3], a01); a11 = fmaf(v.w, w1[4*q+3], a11);
                }
                if (pa) {                             // lane-consecutive p: conflict-free
                    gA[(s * BL + b)     * PPAD + p] = a00;
                    gB[(s * BL + b)     * PPAD + p] = a10;
                    gA[(s * BL + b + 1) * PPAD + p] = a01;
                    gB[(s * BL + b + 1) * PPAD + p] = a11;
                }
            }
        }
        __syncthreads();   // B: partials ready; GEMM done reading h(t-1)

        // ---- fused FC output: row 204 lives at gA[.][b][102] ----
        if (t > 0 && tid < BL) {
            float y = gA[(0 * BL + tid) * PPAD + 102]
                    + gA[(1 * BL + tid) * PPAD + 102];
            out[(size_t)(b0 + tid) * SEQ + (t - 1)] = y;
        }

        // ---- elementwise cell update -> h(t) ----
        if (t < SEQ) {
            #pragma unroll
            for (int r = 0; r < 3; r++) {
                int e = tid + 256 * r;
                if (e < BL * HID) {
                    int b = e / HID, k = e - b * HID;
                    int ri = k,            pi = ri >> 1;
                    int rf = k +     HID,  pf = rf >> 1;
                    int rg = k + 2 * HID,  pg = rg >> 1;
                    int ro = k + 3 * HID,  po = ro >> 1;
                    const float* Ai = (ri & 1) ? gB : gA;
                    const float* Af = (rf & 1) ? gB : gA;
                    const float* Ag = (rg & 1) ? gB : gA;
                    const float* Ao = (ro & 1) ? gB : gA;
                    float gi = Ai[b * PPAD + pi] + Ai[(BL + b) * PPAD + pi];
                    float gf = Af[b * PPAD + pf] + Af[(BL + b) * PPAD + pf];
                    float gg = Ag[b * PPAD + pg] + Ag[(BL + b) * PPAD + pg];
                    float go = Ao[b * PPAD + po] + Ao[(BL + b) * PPAD + po];
                    float c  = sigf(gf) * creg[r] + sigf(gi) * tanhg(gg);
                    creg[r]  = c;
                    h_sh[b * HPAD + k] = sigf(go) * tanhg(c);
                }
            }
        }
    }
}

extern "C" void kernel_launch(void* const* d_in, const int* in_sizes, int n_in,
                              void* d_out, int out_size) {
    const float* input = (const float*)d_in[0];
    const float* W_ih  = (const float*)d_in[1];
    const float* W_hh  = (const float*)d_in[2];
    const float* b_ih  = (const float*)d_in[3];
    const float* b_hh  = (const float*)d_in[4];
    const float* W_fc  = (const float*)d_in[5];
    const float* b_fc  = (const float*)d_in[6];
    lstm_kernel<<<NBLK, 256>>>(input, W_ih, W_hh, b_ih, b_hh, W_fc, b_fc,
                               (float*)d_out);
}